// round 2
// baseline (speedup 1.0000x reference)
#include <cuda_runtime.h>

#define N_NODES 50000
#define N_EDGES 800000
#define DIM     256
#define HID     128
#define TILE_E  32
#define NTHR    256
#define LDN     260   // padded row stride (floats), 16B-aligned rows

__device__ float g_den[N_NODES];
__device__ int   g_is64;

// ---------------------------------------------------------------------------
// Kernel 0: detect edge_index dtype (int32 vs int64).
// For int64 data with values < 2^31, the high 32-bit word of every entry is 0.
// For int32 random indices, odd words are indices (virtually never all zero).
// ---------------------------------------------------------------------------
__global__ void detect_kernel(const int* __restrict__ ei32) {
    int all_hi_zero = 1;
    #pragma unroll 8
    for (int i = 0; i < 512; ++i) {
        if (ei32[2 * i + 1] != 0) { all_hi_zero = 0; break; }
    }
    g_is64 = all_hi_zero;
}

// ---------------------------------------------------------------------------
// Kernel 1: zero the output accumulator and the per-node denominator.
// ---------------------------------------------------------------------------
__global__ void zero_kernel(float4* __restrict__ out4) {
    const int total4 = N_NODES * (DIM / 4);
    int idx = blockIdx.x * blockDim.x + threadIdx.x;
    const int stride = gridDim.x * blockDim.x;
    float4 z = make_float4(0.f, 0.f, 0.f, 0.f);
    for (int i = idx; i < total4; i += stride) out4[i] = z;
    for (int i = idx; i < N_NODES; i += stride) g_den[i] = 0.f;
}

// ---------------------------------------------------------------------------
// Kernel 2: per-edge attention + scatter.
// One block = 32 edges. Gather neigh -> smem, fp32 register-tiled GEMM
// h = relu(neigh@W1+b1), w = sigmoid(h@W2+b2) via warp shuffle reduce,
// then vectorized red.global.add.v4.f32 scatter of neigh*w and w.
// ---------------------------------------------------------------------------
__global__ __launch_bounds__(NTHR, 4)
void edge_kernel(const float* __restrict__ x,
                 const void* __restrict__ ei_raw,
                 const float* __restrict__ W1,
                 const float* __restrict__ b1,
                 const float* __restrict__ W2,
                 const float* __restrict__ b2,
                 float* __restrict__ out)
{
    __shared__ float s_neigh[TILE_E][LDN];
    __shared__ float s_w[TILE_E];
    __shared__ int   s_row[TILE_E];
    __shared__ int   s_col[TILE_E];

    const int tid = threadIdx.x;
    const int eg  = tid >> 5;   // warp id 0..7 -> edges eg*4 .. eg*4+3
    const int jg  = tid & 31;   // lane -> hidden cols j = jg*4 .. jg*4+3
    const long long ebase = (long long)blockIdx.x * TILE_E;

    // --- load edge indices, dtype-dispatched ---
    if (tid < 2 * TILE_E) {
        const int which = (tid < TILE_E) ? 0 : 1;   // 0 = row, 1 = col
        const int t     = which ? (tid - TILE_E) : tid;
        const long long pos = (long long)which * N_EDGES + ebase + t;
        int v;
        if (g_is64) v = (int)((const long long*)ei_raw)[pos];
        else        v = ((const int*)ei_raw)[pos];
        // defensive clamp: a wrong dtype guess becomes rel_err, not an IMA
        v = min(max(v, 0), N_NODES - 1);
        if (which) s_col[t] = v; else s_row[t] = v;
    }
    __syncthreads();

    // --- gather: 32 edges x 64 float4 each = 2048 float4, 8 iters ---
    #pragma unroll
    for (int it = 0; it < (TILE_E * (DIM / 4)) / NTHR; ++it) {
        int f = it * NTHR + tid;
        int e = f >> 6;         // / 64
        int q = f & 63;
        float4 v = __ldg(((const float4*)(x + (long long)s_col[e] * DIM)) + q);
        *(float4*)&s_neigh[e][q * 4] = v;
    }
    __syncthreads();

    // --- GEMM1: acc[e][j] = sum_k neigh[e][k] * W1[k][j] ---
    float acc[4][4];
    #pragma unroll
    for (int e = 0; e < 4; ++e)
        #pragma unroll
        for (int j = 0; j < 4; ++j) acc[e][j] = 0.f;

    const float4* W1v = (const float4*)W1;   // row k: W1v[k*(HID/4) + jg]
    #pragma unroll 4
    for (int k4 = 0; k4 < DIM / 4; ++k4) {
        const int k = k4 * 4;
        float w1r[4][4];
        #pragma unroll
        for (int kk = 0; kk < 4; ++kk)
            *(float4*)w1r[kk] = __ldg(&W1v[(k + kk) * (HID / 4) + jg]);
        #pragma unroll
        for (int e = 0; e < 4; ++e) {
            float4 nv = *(const float4*)&s_neigh[eg * 4 + e][k];  // broadcast
            float nvv[4] = {nv.x, nv.y, nv.z, nv.w};
            #pragma unroll
            for (int kk = 0; kk < 4; ++kk)
                #pragma unroll
                for (int j = 0; j < 4; ++j)
                    acc[e][j] = fmaf(nvv[kk], w1r[kk][j], acc[e][j]);
        }
    }

    // --- epilogue: relu(acc + b1) . W2, warp-reduce over 32 lanes (full j) ---
    float4 b1v = __ldg(((const float4*)b1) + jg);
    float4 w2v = __ldg(((const float4*)W2) + jg);
    float b1a[4] = {b1v.x, b1v.y, b1v.z, b1v.w};
    float w2a[4] = {w2v.x, w2v.y, w2v.z, w2v.w};

    float psum[4];
    #pragma unroll
    for (int e = 0; e < 4; ++e) {
        float s = 0.f;
        #pragma unroll
        for (int j = 0; j < 4; ++j) {
            float h = acc[e][j] + b1a[j];
            h = fmaxf(h, 0.f);
            s = fmaf(h, w2a[j], s);
        }
        psum[e] = s;
    }
    #pragma unroll
    for (int off = 16; off > 0; off >>= 1)
        #pragma unroll
        for (int e = 0; e < 4; ++e)
            psum[e] += __shfl_xor_sync(0xffffffffu, psum[e], off);

    float b2v = __ldg(b2);
    if (jg < 4) {
        float logit = psum[jg] + b2v;
        s_w[eg * 4 + jg] = 1.f / (1.f + expf(-logit));
    }
    __syncthreads();

    // --- scatter: out[row] += neigh * w (vectorized red), den[row] += w ---
    #pragma unroll
    for (int it = 0; it < (TILE_E * (DIM / 4)) / NTHR; ++it) {
        int f = it * NTHR + tid;
        int e = f >> 6;
        int q = f & 63;
        float w = s_w[e];
        float4 nv = *(const float4*)&s_neigh[e][q * 4];
        float4 v = make_float4(nv.x * w, nv.y * w, nv.z * w, nv.w * w);
        float* dst = out + (long long)s_row[e] * DIM + q * 4;
        asm volatile("red.global.add.v4.f32 [%0], {%1, %2, %3, %4};"
                     :: "l"(dst), "f"(v.x), "f"(v.y), "f"(v.z), "f"(v.w)
                     : "memory");
    }
    if (tid < TILE_E) {
        atomicAdd(&g_den[s_row[tid]], s_w[tid]);
    }
}

// ---------------------------------------------------------------------------
// Kernel 3: out = den > 0 ? num / max(den, 1e-12) : 0
// ---------------------------------------------------------------------------
__global__ void finalize_kernel(float4* __restrict__ out4) {
    const int total4 = N_NODES * (DIM / 4);
    int idx = blockIdx.x * blockDim.x + threadIdx.x;
    if (idx >= total4) return;
    int row = idx >> 6;                 // / (DIM/4)
    float den = g_den[row];
    float4 v = out4[idx];
    if (den > 0.f) {
        float inv = 1.f / fmaxf(den, 1e-12f);
        v.x *= inv; v.y *= inv; v.z *= inv; v.w *= inv;
    } else {
        v = make_float4(0.f, 0.f, 0.f, 0.f);
    }
    out4[idx] = v;
}

// ---------------------------------------------------------------------------
extern "C" void kernel_launch(void* const* d_in, const int* in_sizes, int n_in,
                              void* d_out, int out_size) {
    const float* x   = (const float*)d_in[0];
    const void*  ei  = d_in[1];
    const float* W1  = (const float*)d_in[2];
    const float* b1  = (const float*)d_in[3];
    const float* W2  = (const float*)d_in[4];
    const float* b2  = (const float*)d_in[5];
    float*       out = (float*)d_out;

    detect_kernel<<<1, 1>>>((const int*)ei);
    zero_kernel<<<2048, 256>>>((float4*)out);

    const int nblocks = N_EDGES / TILE_E;   // 800000 / 32 = 25000, exact
    edge_kernel<<<nblocks, NTHR>>>(x, ei, W1, b1, W2, b2, out);

    const int total4 = N_NODES * (DIM / 4);
    finalize_kernel<<<(total4 + 255) / 256, 256>>>((float4*)out);
}

// round 3
// speedup vs baseline: 5.4406x; 5.4406x over previous
#include <cuda_runtime.h>

#define N_NODES 50000
#define N_EDGES 800000
#define DIM     256
#define HID     128
#define TILE_N  32
#define NTHR    256
#define LDN     260   // padded row stride (floats)

__device__ float g_den[N_NODES];
__device__ float g_wnode[N_NODES];
__device__ int   g_is64;

// ---------------------------------------------------------------------------
// Kernel 0: detect edge_index dtype (int32 vs int64).
// ---------------------------------------------------------------------------
__global__ void detect_kernel(const int* __restrict__ ei32) {
    int all_hi_zero = 1;
    #pragma unroll 8
    for (int i = 0; i < 512; ++i) {
        if (ei32[2 * i + 1] != 0) { all_hi_zero = 0; break; }
    }
    g_is64 = all_hi_zero;
}

// ---------------------------------------------------------------------------
// Kernel 1: zero output accumulator + per-node denominator.
// ---------------------------------------------------------------------------
__global__ void zero_kernel(float4* __restrict__ out4) {
    const int total4 = N_NODES * (DIM / 4);
    int idx = blockIdx.x * blockDim.x + threadIdx.x;
    const int stride = gridDim.x * blockDim.x;
    float4 z = make_float4(0.f, 0.f, 0.f, 0.f);
    for (int i = idx; i < total4; i += stride) out4[i] = z;
    for (int i = idx; i < N_NODES; i += stride) g_den[i] = 0.f;
}

// ---------------------------------------------------------------------------
// Kernel 2: per-NODE attention weight (the key dedup: w depends only on the
// source node, so compute it once per node instead of once per edge).
// w[n] = sigmoid(relu(x[n]@W1 + b1)@W2 + b2).
// One block = 32 nodes, fp32 register-tiled GEMM (validated in R2 edge kernel).
// ---------------------------------------------------------------------------
__global__ __launch_bounds__(NTHR, 4)
void node_weight_kernel(const float* __restrict__ x,
                        const float* __restrict__ W1,
                        const float* __restrict__ b1,
                        const float* __restrict__ W2,
                        const float* __restrict__ b2)
{
    __shared__ float s_x[TILE_N][LDN];
    __shared__ float s_w[TILE_N];

    const int tid  = threadIdx.x;
    const int eg   = tid >> 5;   // warp -> nodes eg*4 .. eg*4+3 (within tile)
    const int jg   = tid & 31;   // lane -> hidden cols jg*4 .. jg*4+3
    const int base = blockIdx.x * TILE_N;

    // --- load 32 node rows (coalesced, clamp tail) ---
    #pragma unroll
    for (int it = 0; it < (TILE_N * (DIM / 4)) / NTHR; ++it) {
        int f = it * NTHR + tid;
        int e = f >> 6;
        int q = f & 63;
        int node = min(base + e, N_NODES - 1);
        float4 v = __ldg(((const float4*)(x + (long long)node * DIM)) + q);
        *(float4*)&s_x[e][q * 4] = v;
    }
    __syncthreads();

    // --- GEMM: acc[e][j] = sum_k x[e][k] * W1[k][j] ---
    float acc[4][4];
    #pragma unroll
    for (int e = 0; e < 4; ++e)
        #pragma unroll
        for (int j = 0; j < 4; ++j) acc[e][j] = 0.f;

    const float4* W1v = (const float4*)W1;
    #pragma unroll 4
    for (int k4 = 0; k4 < DIM / 4; ++k4) {
        const int k = k4 * 4;
        float w1r[4][4];
        #pragma unroll
        for (int kk = 0; kk < 4; ++kk)
            *(float4*)w1r[kk] = __ldg(&W1v[(k + kk) * (HID / 4) + jg]);
        #pragma unroll
        for (int e = 0; e < 4; ++e) {
            float4 nv = *(const float4*)&s_x[eg * 4 + e][k];
            float nvv[4] = {nv.x, nv.y, nv.z, nv.w};
            #pragma unroll
            for (int kk = 0; kk < 4; ++kk)
                #pragma unroll
                for (int j = 0; j < 4; ++j)
                    acc[e][j] = fmaf(nvv[kk], w1r[kk][j], acc[e][j]);
        }
    }

    // --- epilogue: relu(acc + b1) . W2, warp shuffle reduce, sigmoid ---
    float4 b1v = __ldg(((const float4*)b1) + jg);
    float4 w2v = __ldg(((const float4*)W2) + jg);
    float b1a[4] = {b1v.x, b1v.y, b1v.z, b1v.w};
    float w2a[4] = {w2v.x, w2v.y, w2v.z, w2v.w};

    float psum[4];
    #pragma unroll
    for (int e = 0; e < 4; ++e) {
        float s = 0.f;
        #pragma unroll
        for (int j = 0; j < 4; ++j) {
            float h = fmaxf(acc[e][j] + b1a[j], 0.f);
            s = fmaf(h, w2a[j], s);
        }
        psum[e] = s;
    }
    #pragma unroll
    for (int off = 16; off > 0; off >>= 1)
        #pragma unroll
        for (int e = 0; e < 4; ++e)
            psum[e] += __shfl_xor_sync(0xffffffffu, psum[e], off);

    float b2v = __ldg(b2);
    if (jg < 4) {
        float logit = psum[jg] + b2v;
        s_w[eg * 4 + jg] = 1.f / (1.f + expf(-logit));
    }
    __syncthreads();

    if (tid < TILE_N) {
        int node = base + tid;
        if (node < N_NODES) g_wnode[node] = s_w[tid];
    }
}

// ---------------------------------------------------------------------------
// Kernel 3: edge scatter. One warp per edge: gather x[col], scale by the
// precomputed node weight, red.global.add.v4 into out[row]; den[row] += w.
// Pure memory op: L2-resident gather + LTS reductions.
// ---------------------------------------------------------------------------
__global__ __launch_bounds__(NTHR, 8)
void edge_scatter_kernel(const float* __restrict__ x,
                         const void* __restrict__ ei_raw,
                         float* __restrict__ out)
{
    const int lane   = threadIdx.x & 31;
    const int gwarp  = (blockIdx.x * NTHR + threadIdx.x) >> 5;
    const int nwarps = (gridDim.x * NTHR) >> 5;
    const bool is64  = (g_is64 != 0);

    for (int e = gwarp; e < N_EDGES; e += nwarps) {
        int row, col;
        if (is64) {
            row = (int)((const long long*)ei_raw)[e];
            col = (int)((const long long*)ei_raw)[N_EDGES + e];
        } else {
            row = ((const int*)ei_raw)[e];
            col = ((const int*)ei_raw)[N_EDGES + e];
        }
        row = min(max(row, 0), N_NODES - 1);
        col = min(max(col, 0), N_NODES - 1);

        const float w = __ldg(&g_wnode[col]);
        const float4* src = (const float4*)(x + (long long)col * DIM);
        float*        dst = out + (long long)row * DIM;

        float4 a = __ldg(src + lane);
        float4 b = __ldg(src + lane + 32);
        float4 va = make_float4(a.x * w, a.y * w, a.z * w, a.w * w);
        float4 vb = make_float4(b.x * w, b.y * w, b.z * w, b.w * w);

        asm volatile("red.global.add.v4.f32 [%0], {%1, %2, %3, %4};"
                     :: "l"(dst + lane * 4), "f"(va.x), "f"(va.y), "f"(va.z), "f"(va.w)
                     : "memory");
        asm volatile("red.global.add.v4.f32 [%0], {%1, %2, %3, %4};"
                     :: "l"(dst + (lane + 32) * 4), "f"(vb.x), "f"(vb.y), "f"(vb.z), "f"(vb.w)
                     : "memory");
        if (lane == 0) atomicAdd(&g_den[row], w);
    }
}

// ---------------------------------------------------------------------------
// Kernel 4: out = den > 0 ? num / max(den, 1e-12) : 0
// ---------------------------------------------------------------------------
__global__ void finalize_kernel(float4* __restrict__ out4) {
    const int total4 = N_NODES * (DIM / 4);
    int idx = blockIdx.x * blockDim.x + threadIdx.x;
    if (idx >= total4) return;
    int row = idx >> 6;
    float den = g_den[row];
    float4 v = out4[idx];
    if (den > 0.f) {
        float inv = 1.f / fmaxf(den, 1e-12f);
        v.x *= inv; v.y *= inv; v.z *= inv; v.w *= inv;
    } else {
        v = make_float4(0.f, 0.f, 0.f, 0.f);
    }
    out4[idx] = v;
}

// ---------------------------------------------------------------------------
extern "C" void kernel_launch(void* const* d_in, const int* in_sizes, int n_in,
                              void* d_out, int out_size) {
    const float* x   = (const float*)d_in[0];
    const void*  ei  = d_in[1];
    const float* W1  = (const float*)d_in[2];
    const float* b1  = (const float*)d_in[3];
    const float* W2  = (const float*)d_in[4];
    const float* b2  = (const float*)d_in[5];
    float*       out = (float*)d_out;

    detect_kernel<<<1, 1>>>((const int*)ei);
    zero_kernel<<<2048, 256>>>((float4*)out);

    const int nw_blocks = (N_NODES + TILE_N - 1) / TILE_N;  // 1563
    node_weight_kernel<<<nw_blocks, NTHR>>>(x, W1, b1, W2, b2);

    edge_scatter_kernel<<<12500, NTHR>>>(x, ei, out);

    const int total4 = N_NODES * (DIM / 4);
    finalize_kernel<<<(total4 + 255) / 256, 256>>>((float4*)out);
}

// round 4
// speedup vs baseline: 7.5198x; 1.3822x over previous
#include <cuda_runtime.h>

#define N_NODES 50000
#define N_EDGES 800000
#define DIM     256
#define HID     128
#define TILE_N  32
#define NTHR    256
#define LDN     260
#define SCAN_B  1024
#define NB_SCAN ((N_NODES + SCAN_B - 1) / SCAN_B)   // 49

__device__ float g_wnode[N_NODES];
__device__ int   g_is64;
__device__ int   g_cnt[N_NODES];
__device__ int   g_incl[N_NODES];
__device__ int   g_btot[64];
__device__ int   g_start[N_NODES + 1];
__device__ int   g_cur[N_NODES + 1];
__device__ int   g_scol[N_EDGES];

// ---------------------------------------------------------------------------
// decode helpers
// ---------------------------------------------------------------------------
__device__ __forceinline__ int load_idx(const void* ei, long long pos, bool is64) {
    int v = is64 ? (int)((const long long*)ei)[pos] : ((const int*)ei)[pos];
    return min(max(v, 0), N_NODES - 1);
}

// ---------------------------------------------------------------------------
// Kernel 0: detect int32 vs int64 edge_index; zero counters.
// ---------------------------------------------------------------------------
__global__ void detect_kernel(const int* __restrict__ ei32) {
    int all_hi_zero = 1;
    #pragma unroll 8
    for (int i = 0; i < 512; ++i)
        if (ei32[2 * i + 1] != 0) { all_hi_zero = 0; break; }
    g_is64 = all_hi_zero;
}

__global__ void zero_cnt_kernel() {
    int i = blockIdx.x * blockDim.x + threadIdx.x;
    if (i < N_NODES) g_cnt[i] = 0;
}

// ---------------------------------------------------------------------------
// CSR build: count, scan (3 steps), fill.
// ---------------------------------------------------------------------------
__global__ void count_kernel(const void* __restrict__ ei) {
    int e = blockIdx.x * blockDim.x + threadIdx.x;
    if (e >= N_EDGES) return;
    int row = load_idx(ei, e, g_is64 != 0);
    atomicAdd(&g_cnt[row], 1);
}

__global__ void scan1_kernel() {               // per-block inclusive scan
    __shared__ int s[SCAN_B];
    int t = threadIdx.x, b = blockIdx.x;
    int i = b * SCAN_B + t;
    int v = (i < N_NODES) ? g_cnt[i] : 0;
    s[t] = v;
    __syncthreads();
    #pragma unroll
    for (int off = 1; off < SCAN_B; off <<= 1) {
        int add = (t >= off) ? s[t - off] : 0;
        __syncthreads();
        s[t] += add;
        __syncthreads();
    }
    if (i < N_NODES) g_incl[i] = s[t];
    if (t == SCAN_B - 1) g_btot[b] = s[t];
}

__global__ void scan2_kernel() {               // exclusive scan of 49 block totals
    __shared__ int s[64];
    int t = threadIdx.x;
    s[t] = (t < NB_SCAN) ? g_btot[t] : 0;
    __syncthreads();
    #pragma unroll
    for (int off = 1; off < 64; off <<= 1) {
        int add = (t >= off) ? s[t - off] : 0;
        __syncthreads();
        s[t] += add;
        __syncthreads();
    }
    if (t < NB_SCAN) g_btot[t] = s[t] - ((t < NB_SCAN) ? 0 : 0) - (t < NB_SCAN ? g_btot[t] : 0) + 0; // placeholder, fixed below
}

// NOTE: simpler correct scan2: compute inclusive then convert to exclusive
__global__ void scan2b_kernel() {
    if (threadIdx.x == 0) {
        int run = 0;
        #pragma unroll 1
        for (int b = 0; b < NB_SCAN; ++b) {
            int t = g_btot[b];
            g_btot[b] = run;
            run += t;
        }
    }
}

__global__ void scan3_kernel() {               // g_start[i+1] = incl[i] + boff
    int i = blockIdx.x * blockDim.x + threadIdx.x;
    if (i >= N_NODES) return;
    int v = g_incl[i] + g_btot[i >> 10];
    g_start[i + 1] = v;
    g_cur[i + 1]   = v;
    if (i == 0) { g_start[0] = 0; g_cur[0] = 0; }
}

__global__ void fill_kernel(const void* __restrict__ ei) {
    int e = blockIdx.x * blockDim.x + threadIdx.x;
    if (e >= N_EDGES) return;
    bool is64 = (g_is64 != 0);
    int row = load_idx(ei, e, is64);
    int col = load_idx(ei, (long long)N_EDGES + e, is64);
    int pos = atomicAdd(&g_cur[row], 1);
    g_scol[pos] = col;
}

// ---------------------------------------------------------------------------
// Per-NODE attention weight (validated fp32 register-tiled GEMM).
// ---------------------------------------------------------------------------
__global__ __launch_bounds__(NTHR, 4)
void node_weight_kernel(const float* __restrict__ x,
                        const float* __restrict__ W1,
                        const float* __restrict__ b1,
                        const float* __restrict__ W2,
                        const float* __restrict__ b2)
{
    __shared__ float s_x[TILE_N][LDN];
    __shared__ float s_w[TILE_N];

    const int tid  = threadIdx.x;
    const int eg   = tid >> 5;
    const int jg   = tid & 31;
    const int base = blockIdx.x * TILE_N;

    #pragma unroll
    for (int it = 0; it < (TILE_N * (DIM / 4)) / NTHR; ++it) {
        int f = it * NTHR + tid;
        int e = f >> 6;
        int q = f & 63;
        int node = min(base + e, N_NODES - 1);
        float4 v = __ldg(((const float4*)(x + (long long)node * DIM)) + q);
        *(float4*)&s_x[e][q * 4] = v;
    }
    __syncthreads();

    float acc[4][4];
    #pragma unroll
    for (int e = 0; e < 4; ++e)
        #pragma unroll
        for (int j = 0; j < 4; ++j) acc[e][j] = 0.f;

    const float4* W1v = (const float4*)W1;
    #pragma unroll 4
    for (int k4 = 0; k4 < DIM / 4; ++k4) {
        const int k = k4 * 4;
        float w1r[4][4];
        #pragma unroll
        for (int kk = 0; kk < 4; ++kk)
            *(float4*)w1r[kk] = __ldg(&W1v[(k + kk) * (HID / 4) + jg]);
        #pragma unroll
        for (int e = 0; e < 4; ++e) {
            float4 nv = *(const float4*)&s_x[eg * 4 + e][k];
            float nvv[4] = {nv.x, nv.y, nv.z, nv.w};
            #pragma unroll
            for (int kk = 0; kk < 4; ++kk)
                #pragma unroll
                for (int j = 0; j < 4; ++j)
                    acc[e][j] = fmaf(nvv[kk], w1r[kk][j], acc[e][j]);
        }
    }

    float4 b1v = __ldg(((const float4*)b1) + jg);
    float4 w2v = __ldg(((const float4*)W2) + jg);
    float b1a[4] = {b1v.x, b1v.y, b1v.z, b1v.w};
    float w2a[4] = {w2v.x, w2v.y, w2v.z, w2v.w};

    float psum[4];
    #pragma unroll
    for (int e = 0; e < 4; ++e) {
        float s = 0.f;
        #pragma unroll
        for (int j = 0; j < 4; ++j) {
            float h = fmaxf(acc[e][j] + b1a[j], 0.f);
            s = fmaf(h, w2a[j], s);
        }
        psum[e] = s;
    }
    #pragma unroll
    for (int off = 16; off > 0; off >>= 1)
        #pragma unroll
        for (int e = 0; e < 4; ++e)
            psum[e] += __shfl_xor_sync(0xffffffffu, psum[e], off);

    float b2v = __ldg(b2);
    if (jg < 4) {
        float logit = psum[jg] + b2v;
        s_w[eg * 4 + jg] = 1.f / (1.f + expf(-logit));
    }
    __syncthreads();

    if (tid < TILE_N) {
        int node = base + tid;
        if (node < N_NODES) g_wnode[node] = s_w[tid];
    }
}

// ---------------------------------------------------------------------------
// Aggregation: one warp per destination node. Registers accumulate the
// weighted sum; single plain store; normalization fused (no zero/finalize).
// ---------------------------------------------------------------------------
__global__ __launch_bounds__(NTHR, 8)
void agg_kernel(const float* __restrict__ x, float* __restrict__ out)
{
    const int warp = (blockIdx.x * NTHR + threadIdx.x) >> 5;
    const int lane = threadIdx.x & 31;
    if (warp >= N_NODES) return;

    const int s = g_start[warp];
    const int e = g_start[warp + 1];

    float4 acc0 = make_float4(0.f, 0.f, 0.f, 0.f);
    float4 acc1 = make_float4(0.f, 0.f, 0.f, 0.f);
    float  wsum = 0.f;

    for (int base = s; base < e; base += 32) {
        const int n = min(32, e - base);
        int   col = 0;
        float wv  = 0.f;
        if (lane < n) {
            col = g_scol[base + lane];
            wv  = __ldg(&g_wnode[col]);
        }
        for (int c = 0; c < n; ++c) {
            int   cc = __shfl_sync(0xffffffffu, col, c);
            float ww = __shfl_sync(0xffffffffu, wv,  c);
            const float4* src = (const float4*)(x + (long long)cc * DIM);
            float4 a = __ldg(src + lane);
            float4 b = __ldg(src + lane + 32);
            acc0.x = fmaf(ww, a.x, acc0.x);
            acc0.y = fmaf(ww, a.y, acc0.y);
            acc0.z = fmaf(ww, a.z, acc0.z);
            acc0.w = fmaf(ww, a.w, acc0.w);
            acc1.x = fmaf(ww, b.x, acc1.x);
            acc1.y = fmaf(ww, b.y, acc1.y);
            acc1.z = fmaf(ww, b.z, acc1.z);
            acc1.w = fmaf(ww, b.w, acc1.w);
            wsum += ww;
        }
    }

    float4* dst = (float4*)(out + (long long)warp * DIM);
    if (e > s) {
        float inv = 1.f / fmaxf(wsum, 1e-12f);
        acc0.x *= inv; acc0.y *= inv; acc0.z *= inv; acc0.w *= inv;
        acc1.x *= inv; acc1.y *= inv; acc1.z *= inv; acc1.w *= inv;
        dst[lane]      = acc0;
        dst[lane + 32] = acc1;
    } else {
        float4 z = make_float4(0.f, 0.f, 0.f, 0.f);
        dst[lane]      = z;
        dst[lane + 32] = z;
    }
}

// ---------------------------------------------------------------------------
extern "C" void kernel_launch(void* const* d_in, const int* in_sizes, int n_in,
                              void* d_out, int out_size) {
    const float* x   = (const float*)d_in[0];
    const void*  ei  = d_in[1];
    const float* W1  = (const float*)d_in[2];
    const float* b1  = (const float*)d_in[3];
    const float* W2  = (const float*)d_in[4];
    const float* b2  = (const float*)d_in[5];
    float*       out = (float*)d_out;

    detect_kernel<<<1, 1>>>((const int*)ei);
    zero_cnt_kernel<<<(N_NODES + 255) / 256, 256>>>();
    count_kernel<<<(N_EDGES + NTHR - 1) / NTHR, NTHR>>>(ei);
    scan1_kernel<<<NB_SCAN, SCAN_B>>>();
    scan2b_kernel<<<1, 32>>>();
    scan3_kernel<<<(N_NODES + 255) / 256, 256>>>();
    fill_kernel<<<(N_EDGES + NTHR - 1) / NTHR, NTHR>>>(ei);

    const int nw_blocks = (N_NODES + TILE_N - 1) / TILE_N;
    node_weight_kernel<<<nw_blocks, NTHR>>>(x, W1, b1, W2, b2);

    const int agg_blocks = (N_NODES * 32 + NTHR - 1) / NTHR;  // 6250
    agg_kernel<<<agg_blocks, NTHR>>>(x, out);
}